// round 3
// baseline (speedup 1.0000x reference)
#include <cuda_runtime.h>
#include <cstdint>

#define B_ 32
#define T_ 2048
#define D_ 256
#define H_ 512
#define O_ 256
#define BT_ 65536  // B_*T_

// ---------------- device scratch (static globals; no runtime alloc) ----------------
__device__ __align__(16) float g_xw[(size_t)BT_ * H_];   // input-projection buffer, 128 MB
__device__ volatile unsigned g_flags[128];               // per-CTA arrival counters (monotonic)
__device__ volatile unsigned g_release;                  // publisher release counter (monotonic)

// ============================================================================
// Generic NT GEMM:  C[m][n] = sum_k A[m][k]*B[n][k] + bias1[n] (+ bias2[n])
// Tile 128(M) x 128(N) x 8(K), 256 threads, 8x8 per-thread micro-tile.
// Requires M%128==0, N%128==0, K%8==0. N = gridDim.x*128, M = gridDim.y*128.
// ============================================================================
__global__ __launch_bounds__(256) void gemm_nt_bias(
    const float* __restrict__ A, const float* __restrict__ Bm,
    float* __restrict__ C, int K, int ldc,
    const float* __restrict__ bias1, const float* __restrict__ bias2)
{
    __shared__ float As[8][132];
    __shared__ float Bs[8][132];
    const int tid = threadIdx.x;
    const int m0 = blockIdx.y * 128;
    const int n0 = blockIdx.x * 128;
    const int lr = tid >> 1;              // 0..127 (row within tile)
    const int lk = (tid & 1) * 4;         // 0 or 4 (k quad)
    const float* Ap = A + (size_t)(m0 + lr) * K + lk;
    const float* Bp = Bm + (size_t)(n0 + lr) * K + lk;
    const int ty = tid >> 4, tx = tid & 15;

    float acc[8][8];
#pragma unroll
    for (int i = 0; i < 8; i++)
#pragma unroll
        for (int j = 0; j < 8; j++) acc[i][j] = 0.f;

    for (int k0 = 0; k0 < K; k0 += 8) {
        float4 av = *(const float4*)(Ap + k0);
        float4 bv = *(const float4*)(Bp + k0);
        __syncthreads();
        As[lk + 0][lr] = av.x; As[lk + 1][lr] = av.y;
        As[lk + 2][lr] = av.z; As[lk + 3][lr] = av.w;
        Bs[lk + 0][lr] = bv.x; Bs[lk + 1][lr] = bv.y;
        Bs[lk + 2][lr] = bv.z; Bs[lk + 3][lr] = bv.w;
        __syncthreads();
#pragma unroll
        for (int k = 0; k < 8; k++) {
            float a[8], b[8];
            *(float4*)&a[0] = *(const float4*)&As[k][ty * 8];
            *(float4*)&a[4] = *(const float4*)&As[k][ty * 8 + 4];
            *(float4*)&b[0] = *(const float4*)&Bs[k][tx * 4];
            *(float4*)&b[4] = *(const float4*)&Bs[k][tx * 4 + 64];
#pragma unroll
            for (int i = 0; i < 8; i++)
#pragma unroll
                for (int j = 0; j < 8; j++)
                    acc[i][j] = fmaf(a[i], b[j], acc[i][j]);
        }
    }

    float bsum[8];
#pragma unroll
    for (int j = 0; j < 8; j++) {
        int n = n0 + ((j < 4) ? (tx * 4 + j) : (64 + tx * 4 + (j - 4)));
        float bb = bias1 ? bias1[n] : 0.f;
        if (bias2) bb += bias2[n];
        bsum[j] = bb;
    }
#pragma unroll
    for (int i = 0; i < 8; i++) {
        int m = m0 + ty * 8 + i;
        float4 v0, v1;
        v0.x = acc[i][0] + bsum[0]; v0.y = acc[i][1] + bsum[1];
        v0.z = acc[i][2] + bsum[2]; v0.w = acc[i][3] + bsum[3];
        v1.x = acc[i][4] + bsum[4]; v1.y = acc[i][5] + bsum[5];
        v1.z = acc[i][6] + bsum[6]; v1.w = acc[i][7] + bsum[7];
        *(float4*)(C + (size_t)m * ldc + n0 + tx * 4)      = v0;
        *(float4*)(C + (size_t)m * ldc + n0 + 64 + tx * 4) = v1;
    }
}

// ============================================================================
// Persistent recurrence kernel: h_t = xw_t + h_{t-1} @ W_hh^T, 2048 steps.
// Grid: 128 CTAs x 128 threads, all co-resident (1 per SM).
// CTA c: b in [bg*8, bg*8+8), j in [jg*16, jg*16+16);  bg = c&3, jg = c>>2.
// Per-thread: 4b x 4j register tile over a 32-element K slice (16 slices),
// smem reduction combines slices. W_hh rows cached in smem across all steps.
// Grid barrier: per-CTA flag stores + CTA0 publisher + release broadcast.
// Counters are monotonic and wrap-safe across graph replays.
// ============================================================================
__global__ __launch_bounds__(128) void rnn_scan(
    const float* __restrict__ xw, const float* __restrict__ h0,
    const float* __restrict__ Whh, float* __restrict__ z)
{
    extern __shared__ float sm[];
    float (*Wsm)[516] = (float(*)[516])sm;               // 16 x 516
    float (*hsm)[516] = (float(*)[516])(sm + 16 * 516);  // 8 x 516
    float (*red)[132] = (float(*)[132])(sm + 24 * 516);  // 16 x 132

    const int tid = threadIdx.x;
    const int c = blockIdx.x;
    const int bg = c & 3;
    const int jg = c >> 2;

    // Load this CTA's 16 W_hh rows into smem once (step-invariant).
    for (int i = tid; i < 16 * 128; i += 128) {
        int row = i >> 7, c4 = (i & 127) << 2;
        *(float4*)&Wsm[row][c4] =
            *(const float4*)(Whh + (size_t)(jg * 16 + row) * H_ + c4);
    }

    const unsigned base = g_flags[c];     // replay-persistent monotonic base
    const int ks  = tid >> 3;             // 0..15  K-slice
    const int pos = tid & 7;              // 0..7   output position
    const int pb  = (pos & 1) * 4;        // local b base (0 or 4)
    const int pj  = (pos >> 1) * 4;       // local j base (0,4,8,12)
    const int kc  = ks * 4;               // interleaved k column offset

    for (int t = 0; t < T_; t++) {
        // Load h_{t-1} rows for this CTA's 8 b's (L2 path; no L1 staleness).
        for (int i = tid; i < 1024; i += 128) {
            int rb = i >> 7, c4 = (i & 127) << 2;
            int b = bg * 8 + rb;
            const float4* p = (t == 0)
                ? (const float4*)(h0 + (size_t)b * H_ + c4)
                : (const float4*)(z + ((size_t)b * T_ + (t - 1)) * H_ + c4);
            *(float4*)&hsm[rb][c4] = __ldcg(p);
        }
        __syncthreads();

        float acc[4][4] = {};
#pragma unroll
        for (int g = 0; g < 8; g++) {
            int col = g * 64 + kc;
            float4 h4[4], w4[4];
#pragma unroll
            for (int i = 0; i < 4; i++) h4[i] = *(const float4*)&hsm[pb + i][col];
#pragma unroll
            for (int j = 0; j < 4; j++) w4[j] = *(const float4*)&Wsm[pj + j][col];
#pragma unroll
            for (int i = 0; i < 4; i++)
#pragma unroll
                for (int j = 0; j < 4; j++) {
                    acc[i][j] = fmaf(h4[i].x, w4[j].x, acc[i][j]);
                    acc[i][j] = fmaf(h4[i].y, w4[j].y, acc[i][j]);
                    acc[i][j] = fmaf(h4[i].z, w4[j].z, acc[i][j]);
                    acc[i][j] = fmaf(h4[i].w, w4[j].w, acc[i][j]);
                }
        }

        // Write K-slice partials, reduce across the 16 slices.
#pragma unroll
        for (int i = 0; i < 4; i++)
#pragma unroll
            for (int j = 0; j < 4; j++)
                red[ks][(pb + i) * 16 + pj + j] = acc[i][j];
        __syncthreads();

        float s = 0.f;
#pragma unroll
        for (int q = 0; q < 16; q++) s += red[q][tid];

        const int bl = tid >> 4, jl = tid & 15;
        const size_t r = (size_t)(bg * 8 + bl) * T_ + t;
        const float val = s + xw[r * H_ + jg * 16 + jl];
        z[r * H_ + jg * 16 + jl] = val;

        __threadfence();      // make z visible GPU-wide before arrival
        __syncthreads();      // all CTA writes done before flag

        const unsigned tgt = base + (unsigned)t + 1u;
        if (tid == 0) g_flags[c] = tgt;

        if (c == 0 && tid < 32) {          // publisher: CTA0 warp0
            for (;;) {
                bool ok = true;
                for (int q = tid; q < 128; q += 32)
                    if ((int)(g_flags[q] - tgt) < 0) ok = false;
                if (__all_sync(0xffffffffu, ok)) break;
            }
            if (tid == 0) { __threadfence(); g_release = tgt; }
        }
        if (tid == 0) {
            while ((int)(g_release - tgt) < 0) { }
        }
        __syncthreads();
        __threadfence();      // acquire-side ordering before next step's reads
    }
}

// ============================================================================
// Row softmax over 256 columns; one warp per row, in place.
// ============================================================================
__global__ __launch_bounds__(256) void softmax_rows(float* __restrict__ C)
{
    const int row  = blockIdx.x * 8 + (threadIdx.x >> 5);
    const int lane = threadIdx.x & 31;
    float* p = C + (size_t)row * O_;
    float4 v0 = *(const float4*)(p + lane * 8);
    float4 v1 = *(const float4*)(p + lane * 8 + 4);
    float mx = fmaxf(fmaxf(fmaxf(v0.x, v0.y), fmaxf(v0.z, v0.w)),
                     fmaxf(fmaxf(v1.x, v1.y), fmaxf(v1.z, v1.w)));
#pragma unroll
    for (int o = 16; o; o >>= 1) mx = fmaxf(mx, __shfl_xor_sync(0xffffffffu, mx, o));
    v0.x = __expf(v0.x - mx); v0.y = __expf(v0.y - mx);
    v0.z = __expf(v0.z - mx); v0.w = __expf(v0.w - mx);
    v1.x = __expf(v1.x - mx); v1.y = __expf(v1.y - mx);
    v1.z = __expf(v1.z - mx); v1.w = __expf(v1.w - mx);
    float s = v0.x + v0.y + v0.z + v0.w + v1.x + v1.y + v1.z + v1.w;
#pragma unroll
    for (int o = 16; o; o >>= 1) s += __shfl_xor_sync(0xffffffffu, s, o);
    const float inv = 1.0f / s;
    v0.x *= inv; v0.y *= inv; v0.z *= inv; v0.w *= inv;
    v1.x *= inv; v1.y *= inv; v1.z *= inv; v1.w *= inv;
    *(float4*)(p + lane * 8)     = v0;
    *(float4*)(p + lane * 8 + 4) = v1;
}

// ============================================================================
// Launch: xw GEMM -> persistent scan -> logits GEMM -> softmax
// Output layout: [ out (B,T,O) | z (B,T,H) ]
// ============================================================================
extern "C" void kernel_launch(void* const* d_in, const int* in_sizes, int n_in,
                              void* d_out, int out_size)
{
    (void)in_sizes; (void)n_in; (void)out_size;
    const float* x     = (const float*)d_in[0];
    const float* h0    = (const float*)d_in[1];
    const float* W_ih  = (const float*)d_in[2];
    const float* W_hh  = (const float*)d_in[3];
    const float* b_ih  = (const float*)d_in[4];
    const float* b_hh  = (const float*)d_in[5];
    const float* W_lin = (const float*)d_in[6];
    const float* b_lin = (const float*)d_in[7];

    float* outp = (float*)d_out;
    float* zp   = outp + (size_t)B_ * T_ * O_;

    float* xw = nullptr;
    cudaGetSymbolAddress((void**)&xw, g_xw);

    const int rnn_smem = (24 * 516 + 16 * 132) * 4;  // 57984 bytes
    cudaFuncSetAttribute(rnn_scan, cudaFuncAttributeMaxDynamicSharedMemorySize, rnn_smem);

    // 1) xw[b*T+t][h] = x @ W_ih^T + (b_ih + b_hh)      M=65536, N=512, K=256
    gemm_nt_bias<<<dim3(4, 512), 256>>>(x, W_ih, xw, D_, H_, b_ih, b_hh);

    // 2) sequential recurrence, writes z in place in d_out
    rnn_scan<<<128, 128, rnn_smem>>>(xw, h0, W_hh, zp);

    // 3) logits = z @ W_lin^T + b_lin                    M=65536, N=256, K=512
    gemm_nt_bias<<<dim3(2, 512), 256>>>(zp, W_lin, outp, H_, O_, b_lin, nullptr);

    // 4) softmax over the O dimension, in place
    softmax_rows<<<BT_ / 8, 256>>>(outp);
}